// round 8
// baseline (speedup 1.0000x reference)
#include <cuda_runtime.h>
#include <cuda_bf16.h>
#include <cstdint>
#include <math.h>

#define D_MODEL 1024
#define NH      16
#define DK      64
#define BB      2
#define SS      2048
#define MTOT    (BB * SS)
#define KLOG2   0.41524101186092155f   // log2(10000)/32

// ---------------------------------------------------------------------------
// Scratch (allocation-free rule: __device__ globals)
// ---------------------------------------------------------------------------
__device__ __nv_bfloat16 g_aq_hi[MTOT * D_MODEL], g_aq_lo[MTOT * D_MODEL];
__device__ __nv_bfloat16 g_ak_hi[MTOT * D_MODEL], g_ak_lo[MTOT * D_MODEL];
__device__ __nv_bfloat16 g_av_hi[MTOT * D_MODEL], g_av_lo[MTOT * D_MODEL];
__device__ __nv_bfloat16 g_wq_hi[D_MODEL * D_MODEL], g_wq_lo[D_MODEL * D_MODEL];
__device__ __nv_bfloat16 g_wk_hi[D_MODEL * D_MODEL], g_wk_lo[D_MODEL * D_MODEL];
__device__ __nv_bfloat16 g_wv_hi[D_MODEL * D_MODEL], g_wv_lo[D_MODEL * D_MODEL];
__device__ __nv_bfloat16 g_wo_hi[D_MODEL * D_MODEL], g_wo_lo[D_MODEL * D_MODEL];
__device__ __nv_bfloat16 g_qh_hi[MTOT * D_MODEL], g_qh_lo[MTOT * D_MODEL];
__device__ __nv_bfloat16 g_kh_hi[MTOT * D_MODEL], g_kh_lo[MTOT * D_MODEL];
__device__ __nv_bfloat16 g_vh_hi[MTOT * D_MODEL], g_vh_lo[MTOT * D_MODEL];
__device__ __nv_bfloat16 g_cx_hi[MTOT * D_MODEL], g_cx_lo[MTOT * D_MODEL];

// ---------------------------------------------------------------------------
// Portable PTX helpers
// ---------------------------------------------------------------------------
__device__ __forceinline__ uint32_t smem_u32(const void* p) {
    uint32_t a;
    asm("{ .reg .u64 t; cvta.to.shared.u64 t, %1; cvt.u32.u64 %0, t; }" : "=r"(a) : "l"(p));
    return a;
}
#define CP_ASYNC16(dst, src) \
    asm volatile("cp.async.cg.shared.global [%0], [%1], 16;" :: "r"(dst), "l"(src))
#define CP_COMMIT() asm volatile("cp.async.commit_group;" ::: "memory")
#define CP_WAIT(n)  asm volatile("cp.async.wait_group %0;" :: "n"(n) : "memory")

__device__ __forceinline__ void ldm_x4(uint32_t* r, uint32_t addr) {
    asm volatile("ldmatrix.sync.aligned.m8n8.x4.shared.b16 {%0,%1,%2,%3}, [%4];"
                 : "=r"(r[0]), "=r"(r[1]), "=r"(r[2]), "=r"(r[3]) : "r"(addr));
}
__device__ __forceinline__ void ldm_x4t(uint32_t* r, uint32_t addr) {
    asm volatile("ldmatrix.sync.aligned.m8n8.x4.trans.shared.b16 {%0,%1,%2,%3}, [%4];"
                 : "=r"(r[0]), "=r"(r[1]), "=r"(r[2]), "=r"(r[3]) : "r"(addr));
}
__device__ __forceinline__ void mma16816(float* d, const uint32_t* a, const uint32_t* b) {
    asm volatile(
        "mma.sync.aligned.m16n8k16.row.col.f32.bf16.bf16.f32 "
        "{%0,%1,%2,%3}, {%4,%5,%6,%7}, {%8,%9}, {%0,%1,%2,%3};"
        : "+f"(d[0]), "+f"(d[1]), "+f"(d[2]), "+f"(d[3])
        : "r"(a[0]), "r"(a[1]), "r"(a[2]), "r"(a[3]), "r"(b[0]), "r"(b[1]));
}
__device__ __forceinline__ uint32_t sw64(uint32_t off)  { return off ^ ((off >> 3) & 0x30); }
__device__ __forceinline__ uint32_t sw128(uint32_t off) { return off ^ ((off >> 3) & 0x70); }

__device__ __forceinline__ uint32_t pack_bf16(float lo, float hi) {
    uint32_t r;
    asm("cvt.rn.bf16x2.f32 %0, %1, %2;" : "=r"(r) : "f"(hi), "f"(lo));
    return r;
}
__device__ __forceinline__ void split2(float a, float b, uint32_t& H, uint32_t& L) {
    uint32_t h = pack_bf16(a, b);
    float ha = __int_as_float((int)(h << 16));
    float hb = __int_as_float((int)(h & 0xFFFF0000u));
    H = h;
    L = pack_bf16(a - ha, b - hb);
}
__device__ __forceinline__ float fexp(float x) {
    float t = fmaxf(x * 1.4426950408889634f, -120.0f);
    float y = t + 12582912.0f;
    int   i = __float_as_int(y) - 0x4B400000;
    float f = t - (y - 12582912.0f);
    float p =         1.3333558146e-3f;
    p = fmaf(p, f, 9.6181291076e-3f);
    p = fmaf(p, f, 5.5504108664e-2f);
    p = fmaf(p, f, 2.4022650696e-1f);
    p = fmaf(p, f, 6.9314718056e-1f);
    p = fmaf(p, f, 1.0f);
    return __int_as_float(__float_as_int(p) + (i << 23));
}

// ---------------------------------------------------------------------------
// Fused input splits
// ---------------------------------------------------------------------------
__device__ __forceinline__ void do_split4(float4 v, uint2& H, uint2& L) {
    __nv_bfloat16 h0 = __float2bfloat16(v.x), h1 = __float2bfloat16(v.y);
    __nv_bfloat16 h2 = __float2bfloat16(v.z), h3 = __float2bfloat16(v.w);
    __nv_bfloat16 l0 = __float2bfloat16(v.x - __bfloat162float(h0));
    __nv_bfloat16 l1 = __float2bfloat16(v.y - __bfloat162float(h1));
    __nv_bfloat16 l2 = __float2bfloat16(v.z - __bfloat162float(h2));
    __nv_bfloat16 l3 = __float2bfloat16(v.w - __bfloat162float(h3));
    H.x = (uint32_t)__bfloat16_as_ushort(h0) | ((uint32_t)__bfloat16_as_ushort(h1) << 16);
    H.y = (uint32_t)__bfloat16_as_ushort(h2) | ((uint32_t)__bfloat16_as_ushort(h3) << 16);
    L.x = (uint32_t)__bfloat16_as_ushort(l0) | ((uint32_t)__bfloat16_as_ushort(l1) << 16);
    L.y = (uint32_t)__bfloat16_as_ushort(l2) | ((uint32_t)__bfloat16_as_ushort(l3) << 16);
}

__global__ void split3_kernel(const float4* __restrict__ A, const float4* __restrict__ B,
                              const float4* __restrict__ C, int n4) {
    int i = blockIdx.x * blockDim.x + threadIdx.x;
    if (i >= n4) return;
    const float4* src = (blockIdx.y == 0) ? A : (blockIdx.y == 1) ? B : C;
    uint2* dh = (blockIdx.y == 0) ? (uint2*)g_aq_hi : (blockIdx.y == 1) ? (uint2*)g_ak_hi : (uint2*)g_av_hi;
    uint2* dl = (blockIdx.y == 0) ? (uint2*)g_aq_lo : (blockIdx.y == 1) ? (uint2*)g_ak_lo : (uint2*)g_av_lo;
    uint2 H, L;
    do_split4(src[i], H, L);
    dh[i] = H;
    dl[i] = L;
}

__global__ void split4_kernel(const float4* __restrict__ A, const float4* __restrict__ B,
                              const float4* __restrict__ C, const float4* __restrict__ D, int n4) {
    int i = blockIdx.x * blockDim.x + threadIdx.x;
    if (i >= n4) return;
    int s = blockIdx.y;
    const float4* src = (s == 0) ? A : (s == 1) ? B : (s == 2) ? C : D;
    uint2* oh = (s == 0) ? (uint2*)g_wq_hi : (s == 1) ? (uint2*)g_wk_hi : (s == 2) ? (uint2*)g_wv_hi : (uint2*)g_wo_hi;
    uint2* ol = (s == 0) ? (uint2*)g_wq_lo : (s == 1) ? (uint2*)g_wk_lo : (s == 2) ? (uint2*)g_wv_lo : (uint2*)g_wo_lo;
    uint2 H, L;
    do_split4(src[i], H, L);
    oh[i] = H;
    ol[i] = L;
}

// ---------------------------------------------------------------------------
// GEMM core (unchanged, R6-proven)
// ---------------------------------------------------------------------------
#define GK        1024
#define BKC       32
#define NCH       (GK / BKC)
#define TILE8K    8192
#define STAGE_B   (4 * TILE8K)
#define NSTG      3
#define GEMM_SMEM (NSTG * STAGE_B)

struct GemmCtx {
    uint32_t smb;
    uint32_t aoff[2][2], boff[4][2];
    const __nv_bfloat16* gb[4];
    int lrow, lc;
};

__device__ __forceinline__ void gemm_mainloop(GemmCtx& cx, float acc[2][8][4]) {
    auto load_stage = [&](int st, int ch) {
        const uint32_t sb = cx.smb + st * STAGE_B;
#pragma unroll
        for (int j = 0; j < 8; j++) {
            const int tile = j >> 1;
            const int rh = (j & 1) * 64 + cx.lrow;
            const __nv_bfloat16* g = cx.gb[tile] + (size_t)rh * GK + ch * BKC + cx.lc * 8;
            const uint32_t dst = sb + tile * TILE8K + sw64(rh * 64 + cx.lc * 16);
            CP_ASYNC16(dst, g);
        }
        CP_COMMIT();
    };

    load_stage(0, 0);
    load_stage(1, 1);

    for (int ch = 0; ch < NCH; ch++) {
        if (ch < NCH - 2) { CP_WAIT(1); } else { CP_WAIT(0); }
        __syncthreads();
        if (ch + 2 < NCH) load_stage((ch + 2) % NSTG, ch + 2);

        const uint32_t sb = cx.smb + (ch % NSTG) * STAGE_B;
#pragma unroll
        for (int ks = 0; ks < 2; ks++) {
            uint32_t ah[2][4], al[2][4];
#pragma unroll
            for (int mf = 0; mf < 2; mf++) {
                ldm_x4(ah[mf], sb + cx.aoff[mf][ks]);
                ldm_x4(al[mf], sb + TILE8K + cx.aoff[mf][ks]);
            }
#pragma unroll
            for (int nh = 0; nh < 2; nh++) {
                uint32_t bh[2][4], bl[2][4];
#pragma unroll
                for (int p = 0; p < 2; p++) {
                    ldm_x4(bh[p], sb + 2 * TILE8K + cx.boff[nh * 2 + p][ks]);
                    ldm_x4(bl[p], sb + 3 * TILE8K + cx.boff[nh * 2 + p][ks]);
                }
#pragma unroll
                for (int mf = 0; mf < 2; mf++)
#pragma unroll
                    for (int p = 0; p < 2; p++)
#pragma unroll
                        for (int q = 0; q < 2; q++) {
                            const int nf = nh * 4 + p * 2 + q;
                            mma16816(acc[mf][nf], ah[mf], &bh[p][q * 2]);
                            mma16816(acc[mf][nf], al[mf], &bh[p][q * 2]);
                            mma16816(acc[mf][nf], ah[mf], &bl[p][q * 2]);
                        }
            }
        }
    }
}

__device__ __forceinline__ void gemm_setup(GemmCtx& cx, const char* smc, int t,
                                           const __nv_bfloat16* Ahi, const __nv_bfloat16* Alo,
                                           const __nv_bfloat16* Bhi, const __nv_bfloat16* Blo,
                                           int m0, int n0) {
    cx.smb = smem_u32(smc);
    const int lane = t & 31, wid = t >> 5;
    const int warpM = wid >> 1, warpN = wid & 1;
    cx.lrow = t >> 2;
    cx.lc = t & 3;
    cx.gb[0] = Ahi + (size_t)m0 * GK;
    cx.gb[1] = Alo + (size_t)m0 * GK;
    cx.gb[2] = Bhi + (size_t)n0 * GK;
    cx.gb[3] = Blo + (size_t)n0 * GK;
#pragma unroll
    for (int mf = 0; mf < 2; mf++)
#pragma unroll
        for (int ks = 0; ks < 2; ks++)
            cx.aoff[mf][ks] = sw64((warpM * 32 + mf * 16 + (lane & 15)) * 64
                                   + ks * 32 + (lane >> 4) * 16);
#pragma unroll
    for (int p = 0; p < 4; p++)
#pragma unroll
        for (int ks = 0; ks < 2; ks++)
            cx.boff[p][ks] = sw64((warpN * 64 + p * 16 + ((lane >> 4) << 3) + (lane & 7)) * 64
                                  + ks * 32 + ((lane >> 3) & 1) * 16);
}

// ---------------------------------------------------------------------------
// Merged QKV projection GEMM
// ---------------------------------------------------------------------------
__global__ void __launch_bounds__(256, 2) gemm_qkv_kernel() {
    extern __shared__ char smc[];
    const int t = threadIdx.x;
    const int lane = t & 31, wid = t >> 5;
    const int warpM = wid >> 1, warpN = wid & 1;
    const int m0 = blockIdx.y * 128;
    const int n0 = blockIdx.x * 128;
    const int z = blockIdx.z;

    const __nv_bfloat16 *Ahi, *Alo, *Bhi, *Blo;
    __nv_bfloat16 *Ohi, *Olo;
    float scale;
    if (z == 0) {
        Ahi = g_aq_hi; Alo = g_aq_lo; Bhi = g_wq_hi; Blo = g_wq_lo;
        Ohi = g_qh_hi; Olo = g_qh_lo; scale = 0.125f;
    } else if (z == 1) {
        Ahi = g_ak_hi; Alo = g_ak_lo; Bhi = g_wk_hi; Blo = g_wk_lo;
        Ohi = g_kh_hi; Olo = g_kh_lo; scale = 1.0f;
    } else {
        Ahi = g_av_hi; Alo = g_av_lo; Bhi = g_wv_hi; Blo = g_wv_lo;
        Ohi = g_vh_hi; Olo = g_vh_lo; scale = 1.0f;
    }

    GemmCtx cx;
    gemm_setup(cx, smc, t, Ahi, Alo, Bhi, Blo, m0, n0);

    float acc[2][8][4];
#pragma unroll
    for (int mf = 0; mf < 2; mf++)
#pragma unroll
        for (int nf = 0; nf < 8; nf++)
#pragma unroll
            for (int r = 0; r < 4; r++) acc[mf][nf][r] = 0.0f;

    gemm_mainloop(cx, acc);

    const int rbase = m0 + warpM * 32 + (lane >> 2);
    const int h = (n0 >> 6) + warpN;
    if (z < 2) {
#pragma unroll
        for (int mf = 0; mf < 2; mf++)
#pragma unroll
            for (int r2 = 0; r2 < 2; r2++) {
                const int gr = rbase + mf * 16 + r2 * 8;
                const int s = gr & (SS - 1), b = gr >> 11;
                const float fs = (float)s;
                __nv_bfloat16* oh = Ohi + ((size_t)(b * NH + h) * SS + s) * DK;
                __nv_bfloat16* ol = Olo + ((size_t)(b * NH + h) * SS + s) * DK;
#pragma unroll
                for (int nf = 0; nf < 4; nf++) {
                    const int i0 = (lane & 3) * 2 + nf * 8;
                    float x1a = acc[mf][nf][2 * r2],     x1b = acc[mf][nf][2 * r2 + 1];
                    float x2a = acc[mf][nf + 4][2 * r2], x2b = acc[mf][nf + 4][2 * r2 + 1];
                    float sa, ca, sb2, cb;
                    sincosf(fs * exp2f(-(float)i0 * KLOG2), &sa, &ca);
                    sincosf(fs * exp2f(-(float)(i0 + 1) * KLOG2), &sb2, &cb);
                    float y1a = (x1a * ca - x2a * sa) * scale;
                    float y1b = (x1b * cb - x2b * sb2) * scale;
                    float y2a = (x2a * ca + x1a * sa) * scale;
                    float y2b = (x2b * cb + x1b * sb2) * scale;
                    uint32_t H, L;
                    split2(y1a, y1b, H, L);
                    *(uint32_t*)(oh + i0) = H;
                    *(uint32_t*)(ol + i0) = L;
                    split2(y2a, y2b, H, L);
                    *(uint32_t*)(oh + i0 + 32) = H;
                    *(uint32_t*)(ol + i0 + 32) = L;
                }
            }
    } else {
#pragma unroll
        for (int mf = 0; mf < 2; mf++)
#pragma unroll
            for (int r2 = 0; r2 < 2; r2++) {
                const int gr = rbase + mf * 16 + r2 * 8;
                const int s = gr & (SS - 1), b = gr >> 11;
                __nv_bfloat16* oh = Ohi + ((size_t)(b * NH + h) * SS + s) * DK;
                __nv_bfloat16* ol = Olo + ((size_t)(b * NH + h) * SS + s) * DK;
#pragma unroll
                for (int nf = 0; nf < 8; nf++) {
                    const int d = (lane & 3) * 2 + nf * 8;
                    uint32_t H, L;
                    split2(acc[mf][nf][2 * r2], acc[mf][nf][2 * r2 + 1], H, L);
                    *(uint32_t*)(oh + d) = H;
                    *(uint32_t*)(ol + d) = L;
                }
            }
    }
}

// ---------------------------------------------------------------------------
// Output GEMM
// ---------------------------------------------------------------------------
__global__ void __launch_bounds__(256, 2) gemm_out_kernel(float* __restrict__ C) {
    extern __shared__ char smc[];
    const int t = threadIdx.x;
    const int lane = t & 31, wid = t >> 5;
    const int warpM = wid >> 1, warpN = wid & 1;
    const int m0 = blockIdx.y * 128;
    const int n0 = blockIdx.x * 128;

    GemmCtx cx;
    gemm_setup(cx, smc, t, g_cx_hi, g_cx_lo, g_wo_hi, g_wo_lo, m0, n0);

    float acc[2][8][4];
#pragma unroll
    for (int mf = 0; mf < 2; mf++)
#pragma unroll
        for (int nf = 0; nf < 8; nf++)
#pragma unroll
            for (int r = 0; r < 4; r++) acc[mf][nf][r] = 0.0f;

    gemm_mainloop(cx, acc);

    const int rbase = m0 + warpM * 32 + (lane >> 2);
    const int cbase = n0 + warpN * 64 + (lane & 3) * 2;
#pragma unroll
    for (int mf = 0; mf < 2; mf++)
#pragma unroll
        for (int nf = 0; nf < 8; nf++) {
            const int row = rbase + mf * 16;
            const int col = cbase + nf * 8;
            float2 v0 = {acc[mf][nf][0], acc[mf][nf][1]};
            float2 v1 = {acc[mf][nf][2], acc[mf][nf][3]};
            *(float2*)(C + (size_t)row * D_MODEL + col) = v0;
            *(float2*)(C + (size_t)(row + 8) * D_MODEL + col) = v1;
        }
}

// ---------------------------------------------------------------------------
// Tensor-core causal flash attention — 256 thr / 128 q-rows, S-PIPELINED:
// QK^T(ch+1) issued before softmax(ch) so FMA overlaps in-flight MMA.
// ---------------------------------------------------------------------------
#define AT_QHI   0
#define AT_QLO   16384
#define AT_STG   32768
#define AT_SMEM  (32768 + 2 * 32768)   // 96KB

__global__ void __launch_bounds__(256, 1) attn_tc_kernel() {
    extern __shared__ char smc[];
    const uint32_t smb = smem_u32(smc);
    const int t = threadIdx.x, lane = t & 31, w = t >> 5;
    const int bx = (int)gridDim.x - 1 - (int)blockIdx.x;
    const int bh = blockIdx.y;
    const int q0 = bx * 128;
    const int ntk = 2 * bx + 2;
    const size_t hoff = (size_t)bh * SS * DK;

    // ---- Q loads ----
    {
        int row = t >> 1;
        const __nv_bfloat16* qh = g_qh_hi + hoff + (size_t)(q0 + row) * DK;
        const __nv_bfloat16* ql = g_qh_lo + hoff + (size_t)(q0 + row) * DK;
#pragma unroll
        for (int j = 0; j < 4; j++) {
            int slot = (t & 1) * 4 + j;
            uint32_t sw = sw128(row * 128 + slot * 16);
            CP_ASYNC16(smb + AT_QHI + sw, qh + slot * 8);
            CP_ASYNC16(smb + AT_QLO + sw, ql + slot * 8);
        }
    }
    const int kvrow = t >> 2;
    const int kvs0 = t & 3;
    auto load_kv = [&](int st, int kt) {
        const uint32_t sb = smb + AT_STG + st * 32768;
        const size_t g = hoff + (size_t)(kt * 64 + kvrow) * DK;
#pragma unroll
        for (int j = 0; j < 2; j++) {
            int slot = kvs0 + j * 4;
            uint32_t sw = sw128(kvrow * 128 + slot * 16);
            CP_ASYNC16(sb + 0 * 8192 + sw, g_kh_hi + g + slot * 8);
            CP_ASYNC16(sb + 1 * 8192 + sw, g_kh_lo + g + slot * 8);
            CP_ASYNC16(sb + 2 * 8192 + sw, g_vh_hi + g + slot * 8);
            CP_ASYNC16(sb + 3 * 8192 + sw, g_vh_lo + g + slot * 8);
        }
        CP_COMMIT();
    };

    load_kv(0, 0);            // group 0 (with Q loads)
    load_kv(1, 1);            // group 1 (ntk >= 2 always)
    CP_WAIT(1);               // Q + KV(0) ready
    __syncthreads();

    // ---- Q fragments ----
    uint32_t qh[4][4], ql[4][4];
    {
        uint32_t base = (w * 16 + (lane & 15)) * 128 + (lane >> 4) * 16;
#pragma unroll
        for (int ks = 0; ks < 4; ks++) {
            uint32_t sw = sw128(base + ks * 32);
            ldm_x4(qh[ks], smb + AT_QHI + sw);
            ldm_x4(ql[ks], smb + AT_QLO + sw);
        }
    }

    float oacc[8][4];
#pragma unroll
    for (int nf = 0; nf < 8; nf++)
#pragma unroll
        for (int r = 0; r < 4; r++) oacc[nf][r] = 0.0f;
    float m0 = -1e30f, m1 = -1e30f, l0 = 0.0f, l1 = 0.0f;

    const int qw = q0 + w * 16;
    const uint32_t krow = ((lane >> 4) << 3) + (lane & 7);
    const uint32_t kcol = ((lane >> 3) & 1) * 16;
    const uint32_t vrow = ((lane >> 3) & 1) * 8 + (lane & 7);
    const uint32_t vcol = (lane >> 4) * 16;

    // ---- S computation (QK^T into given accumulator) ----
    auto compute_S = [&](int ch, float (*sacc)[4]) {
        const uint32_t stg = smb + AT_STG + (ch & 1) * 32768;
#pragma unroll
        for (int nf = 0; nf < 8; nf++)
#pragma unroll
            for (int r = 0; r < 4; r++) sacc[nf][r] = 0.0f;
#pragma unroll
        for (int ks = 0; ks < 4; ks++) {
#pragma unroll
            for (int p = 0; p < 4; p++) {
                uint32_t koff = sw128((p * 16 + krow) * 128 + ks * 32 + kcol);
                uint32_t kh[4], kl[4];
                ldm_x4(kh, stg + 0 * 8192 + koff);
                ldm_x4(kl, stg + 1 * 8192 + koff);
                mma16816(sacc[2 * p],     qh[ks], &kh[0]);
                mma16816(sacc[2 * p],     ql[ks], &kh[0]);
                mma16816(sacc[2 * p],     qh[ks], &kl[0]);
                mma16816(sacc[2 * p + 1], qh[ks], &kh[2]);
                mma16816(sacc[2 * p + 1], ql[ks], &kh[2]);
                mma16816(sacc[2 * p + 1], qh[ks], &kl[2]);
            }
        }
    };

    // ---- softmax + pack + PV for tile ch (S in sacc) ----
    auto soft_pv = [&](int ch, float (*sacc)[4]) {
        const int k0g = ch * 64;
        const uint32_t stg = smb + AT_STG + (ch & 1) * 32768;
        const int r0 = qw + (lane >> 2), r1 = r0 + 8;
        if (k0g + 63 > qw) {
#pragma unroll
            for (int nf = 0; nf < 8; nf++) {
                int key = k0g + nf * 8 + (lane & 3) * 2;
                if (key     > r0) sacc[nf][0] = -1e30f;
                if (key + 1 > r0) sacc[nf][1] = -1e30f;
                if (key     > r1) sacc[nf][2] = -1e30f;
                if (key + 1 > r1) sacc[nf][3] = -1e30f;
            }
        }

        float mx0 = -1e30f, mx1 = -1e30f;
#pragma unroll
        for (int nf = 0; nf < 8; nf++) {
            mx0 = fmaxf(mx0, fmaxf(sacc[nf][0], sacc[nf][1]));
            mx1 = fmaxf(mx1, fmaxf(sacc[nf][2], sacc[nf][3]));
        }
        mx0 = fmaxf(mx0, __shfl_xor_sync(0xffffffffu, mx0, 1));
        mx0 = fmaxf(mx0, __shfl_xor_sync(0xffffffffu, mx0, 2));
        mx1 = fmaxf(mx1, __shfl_xor_sync(0xffffffffu, mx1, 1));
        mx1 = fmaxf(mx1, __shfl_xor_sync(0xffffffffu, mx1, 2));
        float mn0 = fmaxf(m0, mx0), mn1 = fmaxf(m1, mx1);
        float al0 = fexp(m0 - mn0), al1 = fexp(m1 - mn1);
        m0 = mn0; m1 = mn1;

        float rs0 = 0.0f, rs1 = 0.0f;
#pragma unroll
        for (int nf = 0; nf < 8; nf++) {
            sacc[nf][0] = fexp(sacc[nf][0] - mn0);
            sacc[nf][1] = fexp(sacc[nf][1] - mn0);
            sacc[nf][2] = fexp(sacc[nf][2] - mn1);
            sacc[nf][3] = fexp(sacc[nf][3] - mn1);
            rs0 += sacc[nf][0] + sacc[nf][1];
            rs1 += sacc[nf][2] + sacc[nf][3];
        }
        rs0 += __shfl_xor_sync(0xffffffffu, rs0, 1);
        rs0 += __shfl_xor_sync(0xffffffffu, rs0, 2);
        rs1 += __shfl_xor_sync(0xffffffffu, rs1, 1);
        rs1 += __shfl_xor_sync(0xffffffffu, rs1, 2);
        l0 = l0 * al0 + rs0;
        l1 = l1 * al1 + rs1;

#pragma unroll
        for (int nf = 0; nf < 8; nf++) {
            oacc[nf][0] *= al0; oacc[nf][1] *= al0;
            oacc[nf][2] *= al1; oacc[nf][3] *= al1;
        }

        uint32_t ph[4][4], pl[4][4];
#pragma unroll
        for (int kf = 0; kf < 4; kf++) {
#pragma unroll
            for (int half = 0; half < 2; half++) {
                const float* c = sacc[2 * kf + half];
                uint32_t hA, lA, hB, lB;
                split2(c[0], c[1], hA, lA);
                split2(c[2], c[3], hB, lB);
                ph[kf][half * 2 + 0] = hA;
                ph[kf][half * 2 + 1] = hB;
                pl[kf][half * 2 + 0] = lA;
                pl[kf][half * 2 + 1] = lB;
            }
        }

#pragma unroll
        for (int kf = 0; kf < 4; kf++) {
#pragma unroll
            for (int nb = 0; nb < 4; nb++) {
                uint32_t voff = sw128((kf * 16 + vrow) * 128 + nb * 32 + vcol);
                uint32_t vh[4], vl[4];
                ldm_x4t(vh, stg + 2 * 8192 + voff);
                ldm_x4t(vl, stg + 3 * 8192 + voff);
                mma16816(oacc[2 * nb],     ph[kf], &vh[0]);
                mma16816(oacc[2 * nb],     pl[kf], &vh[0]);
                mma16816(oacc[2 * nb],     ph[kf], &vl[0]);
                mma16816(oacc[2 * nb + 1], ph[kf], &vh[2]);
                mma16816(oacc[2 * nb + 1], pl[kf], &vh[2]);
                mma16816(oacc[2 * nb + 1], ph[kf], &vl[2]);
            }
        }
    };

    float sA[8][4], sB[8][4];
    compute_S(0, sA);          // KV(0) resident; KV(1) in flight

    // body: S(ch) lives in `cur`; compute S(ch+1) into `nxt`, then soft+PV(ch)
    auto body = [&](int ch, float (*cur)[4], float (*nxt)[4]) {
        const bool haveNext = (ch + 1 < ntk);
        if (haveNext) {
            CP_WAIT(0);                        // KV(ch+1) arrived
            __syncthreads();
            if ((ch + 1) * 64 <= qw + 15)      // not fully masked for this warp
                compute_S(ch + 1, nxt);
        }
        if (ch * 64 <= qw + 15)
            soft_pv(ch, cur);
        if (ch + 2 < ntk) {
            __syncthreads();                   // V(ch) consumed by all warps
            load_kv(ch & 1, ch + 2);
        }
    };

    for (int ch = 0; ch < ntk; ch += 2) {
        body(ch, sA, sB);
        if (ch + 1 < ntk) body(ch + 1, sB, sA);
    }

    // ---- epilogue: flat bf16 hi/lo splits ----
    const int b = bh >> 4, h = bh & 15;
    const float inv0 = 1.0f / l0, inv1 = 1.0f / l1;
    const int row0 = q0 + w * 16 + (lane >> 2);
    const size_t off0 = ((size_t)(b * SS + row0)) * D_MODEL + h * DK + (lane & 3) * 2;
    const size_t off1 = off0 + 8 * D_MODEL;
#pragma unroll
    for (int nf = 0; nf < 8; nf++) {
        uint32_t H, L;
        split2(oacc[nf][0] * inv0, oacc[nf][1] * inv0, H, L);
        *(uint32_t*)(g_cx_hi + off0 + nf * 8) = H;
        *(uint32_t*)(g_cx_lo + off0 + nf * 8) = L;
        split2(oacc[nf][2] * inv1, oacc[nf][3] * inv1, H, L);
        *(uint32_t*)(g_cx_hi + off1 + nf * 8) = H;
        *(uint32_t*)(g_cx_lo + off1 + nf * 8) = L;
    }
}

// ---------------------------------------------------------------------------
// Launch
// ---------------------------------------------------------------------------
extern "C" void kernel_launch(void* const* d_in, const int* in_sizes, int n_in,
                              void* d_out, int out_size) {
    const float* q  = (const float*)d_in[0];
    const float* k  = (const float*)d_in[1];
    const float* v  = (const float*)d_in[2];
    const float* Wq = (const float*)d_in[4];
    const float* Wk = (const float*)d_in[5];
    const float* Wv = (const float*)d_in[6];
    const float* Wo = (const float*)d_in[7];
    float* out = (float*)d_out;

    cudaFuncSetAttribute(gemm_qkv_kernel, cudaFuncAttributeMaxDynamicSharedMemorySize, GEMM_SMEM);
    cudaFuncSetAttribute(gemm_out_kernel, cudaFuncAttributeMaxDynamicSharedMemorySize, GEMM_SMEM);
    cudaFuncSetAttribute(attn_tc_kernel, cudaFuncAttributeMaxDynamicSharedMemorySize, AT_SMEM);

    const int nA4 = MTOT * D_MODEL / 4;
    const int nW4 = D_MODEL * D_MODEL / 4;

    split3_kernel<<<dim3((nA4 + 255) / 256, 3), 256>>>(
        (const float4*)q, (const float4*)k, (const float4*)v, nA4);
    split4_kernel<<<dim3((nW4 + 255) / 256, 4), 256>>>(
        (const float4*)Wq, (const float4*)Wk, (const float4*)Wv, (const float4*)Wo, nW4);

    gemm_qkv_kernel<<<dim3(D_MODEL / 128, MTOT / 128, 3), 256, GEMM_SMEM>>>();

    attn_tc_kernel<<<dim3(SS / 128, BB * NH), 256, AT_SMEM>>>();

    gemm_out_kernel<<<dim3(D_MODEL / 128, MTOT / 128), 256, GEMM_SMEM>>>(out);
}

// round 9
// speedup vs baseline: 1.0846x; 1.0846x over previous
#include <cuda_runtime.h>
#include <cuda_bf16.h>
#include <cstdint>
#include <math.h>

#define D_MODEL 1024
#define NH      16
#define DK      64
#define BB      2
#define SS      2048
#define MTOT    (BB * SS)
#define KLOG2   0.41524101186092155f   // log2(10000)/32
#define LOG2E   1.4426950408889634f

// ---------------------------------------------------------------------------
// Scratch (allocation-free rule: __device__ globals)
// ---------------------------------------------------------------------------
__device__ __nv_bfloat16 g_aq_hi[MTOT * D_MODEL], g_aq_lo[MTOT * D_MODEL];
__device__ __nv_bfloat16 g_ak_hi[MTOT * D_MODEL], g_ak_lo[MTOT * D_MODEL];
__device__ __nv_bfloat16 g_av_hi[MTOT * D_MODEL], g_av_lo[MTOT * D_MODEL];
__device__ __nv_bfloat16 g_wq_hi[D_MODEL * D_MODEL], g_wq_lo[D_MODEL * D_MODEL];
__device__ __nv_bfloat16 g_wk_hi[D_MODEL * D_MODEL], g_wk_lo[D_MODEL * D_MODEL];
__device__ __nv_bfloat16 g_wv_hi[D_MODEL * D_MODEL], g_wv_lo[D_MODEL * D_MODEL];
__device__ __nv_bfloat16 g_wo_hi[D_MODEL * D_MODEL], g_wo_lo[D_MODEL * D_MODEL];
__device__ __nv_bfloat16 g_qh_hi[MTOT * D_MODEL], g_qh_lo[MTOT * D_MODEL];
__device__ __nv_bfloat16 g_kh_hi[MTOT * D_MODEL], g_kh_lo[MTOT * D_MODEL];
__device__ __nv_bfloat16 g_vh_hi[MTOT * D_MODEL], g_vh_lo[MTOT * D_MODEL];
__device__ __nv_bfloat16 g_cx_hi[MTOT * D_MODEL], g_cx_lo[MTOT * D_MODEL];

// ---------------------------------------------------------------------------
// Portable PTX helpers
// ---------------------------------------------------------------------------
__device__ __forceinline__ uint32_t smem_u32(const void* p) {
    uint32_t a;
    asm("{ .reg .u64 t; cvta.to.shared.u64 t, %1; cvt.u32.u64 %0, t; }" : "=r"(a) : "l"(p));
    return a;
}
#define CP_ASYNC16(dst, src) \
    asm volatile("cp.async.cg.shared.global [%0], [%1], 16;" :: "r"(dst), "l"(src))
#define CP_COMMIT() asm volatile("cp.async.commit_group;" ::: "memory")
#define CP_WAIT(n)  asm volatile("cp.async.wait_group %0;" :: "n"(n) : "memory")

__device__ __forceinline__ void ldm_x4(uint32_t* r, uint32_t addr) {
    asm volatile("ldmatrix.sync.aligned.m8n8.x4.shared.b16 {%0,%1,%2,%3}, [%4];"
                 : "=r"(r[0]), "=r"(r[1]), "=r"(r[2]), "=r"(r[3]) : "r"(addr));
}
__device__ __forceinline__ void ldm_x4t(uint32_t* r, uint32_t addr) {
    asm volatile("ldmatrix.sync.aligned.m8n8.x4.trans.shared.b16 {%0,%1,%2,%3}, [%4];"
                 : "=r"(r[0]), "=r"(r[1]), "=r"(r[2]), "=r"(r[3]) : "r"(addr));
}
__device__ __forceinline__ void mma16816(float* d, const uint32_t* a, const uint32_t* b) {
    asm volatile(
        "mma.sync.aligned.m16n8k16.row.col.f32.bf16.bf16.f32 "
        "{%0,%1,%2,%3}, {%4,%5,%6,%7}, {%8,%9}, {%0,%1,%2,%3};"
        : "+f"(d[0]), "+f"(d[1]), "+f"(d[2]), "+f"(d[3])
        : "r"(a[0]), "r"(a[1]), "r"(a[2]), "r"(a[3]), "r"(b[0]), "r"(b[1]));
}
__device__ __forceinline__ uint32_t sw64(uint32_t off)  { return off ^ ((off >> 3) & 0x30); }
__device__ __forceinline__ uint32_t sw128(uint32_t off) { return off ^ ((off >> 3) & 0x70); }

__device__ __forceinline__ uint32_t pack_bf16(float lo, float hi) {
    uint32_t r;
    asm("cvt.rn.bf16x2.f32 %0, %1, %2;" : "=r"(r) : "f"(hi), "f"(lo));
    return r;
}
__device__ __forceinline__ void split2(float a, float b, uint32_t& H, uint32_t& L) {
    uint32_t h = pack_bf16(a, b);
    float ha = __int_as_float((int)(h << 16));
    float hb = __int_as_float((int)(h & 0xFFFF0000u));
    H = h;
    L = pack_bf16(a - ha, b - hb);
}
// e^x via MUFU ex2 (args always <= 0 here; very negative -> 0, exactly what
// masked entries need). 1 MUFU instead of ~7 FMA.
__device__ __forceinline__ float fex2(float x) {
    float r;
    asm("ex2.approx.f32 %0, %1;" : "=f"(r) : "f"(x));
    return r;
}

// ---------------------------------------------------------------------------
// Fused input splits
// ---------------------------------------------------------------------------
__device__ __forceinline__ void do_split4(float4 v, uint2& H, uint2& L) {
    __nv_bfloat16 h0 = __float2bfloat16(v.x), h1 = __float2bfloat16(v.y);
    __nv_bfloat16 h2 = __float2bfloat16(v.z), h3 = __float2bfloat16(v.w);
    __nv_bfloat16 l0 = __float2bfloat16(v.x - __bfloat162float(h0));
    __nv_bfloat16 l1 = __float2bfloat16(v.y - __bfloat162float(h1));
    __nv_bfloat16 l2 = __float2bfloat16(v.z - __bfloat162float(h2));
    __nv_bfloat16 l3 = __float2bfloat16(v.w - __bfloat162float(h3));
    H.x = (uint32_t)__bfloat16_as_ushort(h0) | ((uint32_t)__bfloat16_as_ushort(h1) << 16);
    H.y = (uint32_t)__bfloat16_as_ushort(h2) | ((uint32_t)__bfloat16_as_ushort(h3) << 16);
    L.x = (uint32_t)__bfloat16_as_ushort(l0) | ((uint32_t)__bfloat16_as_ushort(l1) << 16);
    L.y = (uint32_t)__bfloat16_as_ushort(l2) | ((uint32_t)__bfloat16_as_ushort(l3) << 16);
}

__global__ void split3_kernel(const float4* __restrict__ A, const float4* __restrict__ B,
                              const float4* __restrict__ C, int n4) {
    int i = blockIdx.x * blockDim.x + threadIdx.x;
    if (i >= n4) return;
    const float4* src = (blockIdx.y == 0) ? A : (blockIdx.y == 1) ? B : C;
    uint2* dh = (blockIdx.y == 0) ? (uint2*)g_aq_hi : (blockIdx.y == 1) ? (uint2*)g_ak_hi : (uint2*)g_av_hi;
    uint2* dl = (blockIdx.y == 0) ? (uint2*)g_aq_lo : (blockIdx.y == 1) ? (uint2*)g_ak_lo : (uint2*)g_av_lo;
    uint2 H, L;
    do_split4(src[i], H, L);
    dh[i] = H;
    dl[i] = L;
}

__global__ void split4_kernel(const float4* __restrict__ A, const float4* __restrict__ B,
                              const float4* __restrict__ C, const float4* __restrict__ D, int n4) {
    int i = blockIdx.x * blockDim.x + threadIdx.x;
    if (i >= n4) return;
    int s = blockIdx.y;
    const float4* src = (s == 0) ? A : (s == 1) ? B : (s == 2) ? C : D;
    uint2* oh = (s == 0) ? (uint2*)g_wq_hi : (s == 1) ? (uint2*)g_wk_hi : (s == 2) ? (uint2*)g_wv_hi : (uint2*)g_wo_hi;
    uint2* ol = (s == 0) ? (uint2*)g_wq_lo : (s == 1) ? (uint2*)g_wk_lo : (s == 2) ? (uint2*)g_wv_lo : (uint2*)g_wo_lo;
    uint2 H, L;
    do_split4(src[i], H, L);
    oh[i] = H;
    ol[i] = L;
}

// ---------------------------------------------------------------------------
// GEMM core (R6-proven)
// ---------------------------------------------------------------------------
#define GK        1024
#define BKC       32
#define NCH       (GK / BKC)
#define TILE8K    8192
#define STAGE_B   (4 * TILE8K)
#define NSTG      3
#define GEMM_SMEM (NSTG * STAGE_B)

struct GemmCtx {
    uint32_t smb;
    uint32_t aoff[2][2], boff[4][2];
    const __nv_bfloat16* gb[4];
    int lrow, lc;
};

__device__ __forceinline__ void gemm_mainloop(GemmCtx& cx, float acc[2][8][4]) {
    auto load_stage = [&](int st, int ch) {
        const uint32_t sb = cx.smb + st * STAGE_B;
#pragma unroll
        for (int j = 0; j < 8; j++) {
            const int tile = j >> 1;
            const int rh = (j & 1) * 64 + cx.lrow;
            const __nv_bfloat16* g = cx.gb[tile] + (size_t)rh * GK + ch * BKC + cx.lc * 8;
            const uint32_t dst = sb + tile * TILE8K + sw64(rh * 64 + cx.lc * 16);
            CP_ASYNC16(dst, g);
        }
        CP_COMMIT();
    };

    load_stage(0, 0);
    load_stage(1, 1);

    for (int ch = 0; ch < NCH; ch++) {
        if (ch < NCH - 2) { CP_WAIT(1); } else { CP_WAIT(0); }
        __syncthreads();
        if (ch + 2 < NCH) load_stage((ch + 2) % NSTG, ch + 2);

        const uint32_t sb = cx.smb + (ch % NSTG) * STAGE_B;
#pragma unroll
        for (int ks = 0; ks < 2; ks++) {
            uint32_t ah[2][4], al[2][4];
#pragma unroll
            for (int mf = 0; mf < 2; mf++) {
                ldm_x4(ah[mf], sb + cx.aoff[mf][ks]);
                ldm_x4(al[mf], sb + TILE8K + cx.aoff[mf][ks]);
            }
#pragma unroll
            for (int nh = 0; nh < 2; nh++) {
                uint32_t bh[2][4], bl[2][4];
#pragma unroll
                for (int p = 0; p < 2; p++) {
                    ldm_x4(bh[p], sb + 2 * TILE8K + cx.boff[nh * 2 + p][ks]);
                    ldm_x4(bl[p], sb + 3 * TILE8K + cx.boff[nh * 2 + p][ks]);
                }
#pragma unroll
                for (int mf = 0; mf < 2; mf++)
#pragma unroll
                    for (int p = 0; p < 2; p++)
#pragma unroll
                        for (int q = 0; q < 2; q++) {
                            const int nf = nh * 4 + p * 2 + q;
                            mma16816(acc[mf][nf], ah[mf], &bh[p][q * 2]);
                            mma16816(acc[mf][nf], al[mf], &bh[p][q * 2]);
                            mma16816(acc[mf][nf], ah[mf], &bl[p][q * 2]);
                        }
            }
        }
    }
}

__device__ __forceinline__ void gemm_setup(GemmCtx& cx, const char* smc, int t,
                                           const __nv_bfloat16* Ahi, const __nv_bfloat16* Alo,
                                           const __nv_bfloat16* Bhi, const __nv_bfloat16* Blo,
                                           int m0, int n0) {
    cx.smb = smem_u32(smc);
    const int lane = t & 31, wid = t >> 5;
    const int warpM = wid >> 1, warpN = wid & 1;
    cx.lrow = t >> 2;
    cx.lc = t & 3;
    cx.gb[0] = Ahi + (size_t)m0 * GK;
    cx.gb[1] = Alo + (size_t)m0 * GK;
    cx.gb[2] = Bhi + (size_t)n0 * GK;
    cx.gb[3] = Blo + (size_t)n0 * GK;
#pragma unroll
    for (int mf = 0; mf < 2; mf++)
#pragma unroll
        for (int ks = 0; ks < 2; ks++)
            cx.aoff[mf][ks] = sw64((warpM * 32 + mf * 16 + (lane & 15)) * 64
                                   + ks * 32 + (lane >> 4) * 16);
#pragma unroll
    for (int p = 0; p < 4; p++)
#pragma unroll
        for (int ks = 0; ks < 2; ks++)
            cx.boff[p][ks] = sw64((warpN * 64 + p * 16 + ((lane >> 4) << 3) + (lane & 7)) * 64
                                  + ks * 32 + ((lane >> 3) & 1) * 16);
}

// ---------------------------------------------------------------------------
// Merged QKV projection GEMM
// ---------------------------------------------------------------------------
__global__ void __launch_bounds__(256, 2) gemm_qkv_kernel() {
    extern __shared__ char smc[];
    const int t = threadIdx.x;
    const int lane = t & 31, wid = t >> 5;
    const int warpM = wid >> 1, warpN = wid & 1;
    const int m0 = blockIdx.y * 128;
    const int n0 = blockIdx.x * 128;
    const int z = blockIdx.z;

    const __nv_bfloat16 *Ahi, *Alo, *Bhi, *Blo;
    __nv_bfloat16 *Ohi, *Olo;
    float scale;
    if (z == 0) {
        Ahi = g_aq_hi; Alo = g_aq_lo; Bhi = g_wq_hi; Blo = g_wq_lo;
        Ohi = g_qh_hi; Olo = g_qh_lo; scale = 0.125f;
    } else if (z == 1) {
        Ahi = g_ak_hi; Alo = g_ak_lo; Bhi = g_wk_hi; Blo = g_wk_lo;
        Ohi = g_kh_hi; Olo = g_kh_lo; scale = 1.0f;
    } else {
        Ahi = g_av_hi; Alo = g_av_lo; Bhi = g_wv_hi; Blo = g_wv_lo;
        Ohi = g_vh_hi; Olo = g_vh_lo; scale = 1.0f;
    }

    GemmCtx cx;
    gemm_setup(cx, smc, t, Ahi, Alo, Bhi, Blo, m0, n0);

    float acc[2][8][4];
#pragma unroll
    for (int mf = 0; mf < 2; mf++)
#pragma unroll
        for (int nf = 0; nf < 8; nf++)
#pragma unroll
            for (int r = 0; r < 4; r++) acc[mf][nf][r] = 0.0f;

    gemm_mainloop(cx, acc);

    const int rbase = m0 + warpM * 32 + (lane >> 2);
    const int h = (n0 >> 6) + warpN;
    if (z < 2) {
#pragma unroll
        for (int mf = 0; mf < 2; mf++)
#pragma unroll
            for (int r2 = 0; r2 < 2; r2++) {
                const int gr = rbase + mf * 16 + r2 * 8;
                const int s = gr & (SS - 1), b = gr >> 11;
                const float fs = (float)s;
                __nv_bfloat16* oh = Ohi + ((size_t)(b * NH + h) * SS + s) * DK;
                __nv_bfloat16* ol = Olo + ((size_t)(b * NH + h) * SS + s) * DK;
#pragma unroll
                for (int nf = 0; nf < 4; nf++) {
                    const int i0 = (lane & 3) * 2 + nf * 8;
                    float x1a = acc[mf][nf][2 * r2],     x1b = acc[mf][nf][2 * r2 + 1];
                    float x2a = acc[mf][nf + 4][2 * r2], x2b = acc[mf][nf + 4][2 * r2 + 1];
                    float sa, ca, sb2, cb;
                    sincosf(fs * exp2f(-(float)i0 * KLOG2), &sa, &ca);
                    sincosf(fs * exp2f(-(float)(i0 + 1) * KLOG2), &sb2, &cb);
                    float y1a = (x1a * ca - x2a * sa) * scale;
                    float y1b = (x1b * cb - x2b * sb2) * scale;
                    float y2a = (x2a * ca + x1a * sa) * scale;
                    float y2b = (x2b * cb + x1b * sb2) * scale;
                    uint32_t H, L;
                    split2(y1a, y1b, H, L);
                    *(uint32_t*)(oh + i0) = H;
                    *(uint32_t*)(ol + i0) = L;
                    split2(y2a, y2b, H, L);
                    *(uint32_t*)(oh + i0 + 32) = H;
                    *(uint32_t*)(ol + i0 + 32) = L;
                }
            }
    } else {
#pragma unroll
        for (int mf = 0; mf < 2; mf++)
#pragma unroll
            for (int r2 = 0; r2 < 2; r2++) {
                const int gr = rbase + mf * 16 + r2 * 8;
                const int s = gr & (SS - 1), b = gr >> 11;
                __nv_bfloat16* oh = Ohi + ((size_t)(b * NH + h) * SS + s) * DK;
                __nv_bfloat16* ol = Olo + ((size_t)(b * NH + h) * SS + s) * DK;
#pragma unroll
                for (int nf = 0; nf < 8; nf++) {
                    const int d = (lane & 3) * 2 + nf * 8;
                    uint32_t H, L;
                    split2(acc[mf][nf][2 * r2], acc[mf][nf][2 * r2 + 1], H, L);
                    *(uint32_t*)(oh + d) = H;
                    *(uint32_t*)(ol + d) = L;
                }
            }
    }
}

// ---------------------------------------------------------------------------
// Output GEMM
// ---------------------------------------------------------------------------
__global__ void __launch_bounds__(256, 2) gemm_out_kernel(float* __restrict__ C) {
    extern __shared__ char smc[];
    const int t = threadIdx.x;
    const int lane = t & 31, wid = t >> 5;
    const int warpM = wid >> 1, warpN = wid & 1;
    const int m0 = blockIdx.y * 128;
    const int n0 = blockIdx.x * 128;

    GemmCtx cx;
    gemm_setup(cx, smc, t, g_cx_hi, g_cx_lo, g_wo_hi, g_wo_lo, m0, n0);

    float acc[2][8][4];
#pragma unroll
    for (int mf = 0; mf < 2; mf++)
#pragma unroll
        for (int nf = 0; nf < 8; nf++)
#pragma unroll
            for (int r = 0; r < 4; r++) acc[mf][nf][r] = 0.0f;

    gemm_mainloop(cx, acc);

    const int rbase = m0 + warpM * 32 + (lane >> 2);
    const int cbase = n0 + warpN * 64 + (lane & 3) * 2;
#pragma unroll
    for (int mf = 0; mf < 2; mf++)
#pragma unroll
        for (int nf = 0; nf < 8; nf++) {
            const int row = rbase + mf * 16;
            const int col = cbase + nf * 8;
            float2 v0 = {acc[mf][nf][0], acc[mf][nf][1]};
            float2 v1 = {acc[mf][nf][2], acc[mf][nf][3]};
            *(float2*)(C + (size_t)row * D_MODEL + col) = v0;
            *(float2*)(C + (size_t)(row + 8) * D_MODEL + col) = v1;
        }
}

// ---------------------------------------------------------------------------
// Tensor-core causal flash attention — exact R6 structure; exp via MUFU ex2.
// ---------------------------------------------------------------------------
#define AT_QHI   0
#define AT_QLO   16384
#define AT_STG   32768
#define AT_SMEM  (32768 + 2 * 32768)   // 96KB

__global__ void __launch_bounds__(256, 1) attn_tc_kernel() {
    extern __shared__ char smc[];
    const uint32_t smb = smem_u32(smc);
    const int t = threadIdx.x, lane = t & 31, w = t >> 5;
    const int bx = (int)gridDim.x - 1 - (int)blockIdx.x;
    const int bh = blockIdx.y;
    const int q0 = bx * 128;
    const int ntk = 2 * bx + 2;
    const size_t hoff = (size_t)bh * SS * DK;

    {
        int row = t >> 1;
        const __nv_bfloat16* qh = g_qh_hi + hoff + (size_t)(q0 + row) * DK;
        const __nv_bfloat16* ql = g_qh_lo + hoff + (size_t)(q0 + row) * DK;
#pragma unroll
        for (int j = 0; j < 4; j++) {
            int slot = (t & 1) * 4 + j;
            uint32_t sw = sw128(row * 128 + slot * 16);
            CP_ASYNC16(smb + AT_QHI + sw, qh + slot * 8);
            CP_ASYNC16(smb + AT_QLO + sw, ql + slot * 8);
        }
    }
    const int kvrow = t >> 2;
    const int kvs0 = t & 3;
    auto load_kv = [&](int st, int kt) {
        const uint32_t sb = smb + AT_STG + st * 32768;
        const size_t g = hoff + (size_t)(kt * 64 + kvrow) * DK;
#pragma unroll
        for (int j = 0; j < 2; j++) {
            int slot = kvs0 + j * 4;
            uint32_t sw = sw128(kvrow * 128 + slot * 16);
            CP_ASYNC16(sb + 0 * 8192 + sw, g_kh_hi + g + slot * 8);
            CP_ASYNC16(sb + 1 * 8192 + sw, g_kh_lo + g + slot * 8);
            CP_ASYNC16(sb + 2 * 8192 + sw, g_vh_hi + g + slot * 8);
            CP_ASYNC16(sb + 3 * 8192 + sw, g_vh_lo + g + slot * 8);
        }
        CP_COMMIT();
    };

    load_kv(0, 0);
    CP_WAIT(0);
    __syncthreads();

    uint32_t qh[4][4], ql[4][4];
    {
        uint32_t base = (w * 16 + (lane & 15)) * 128 + (lane >> 4) * 16;
#pragma unroll
        for (int ks = 0; ks < 4; ks++) {
            uint32_t sw = sw128(base + ks * 32);
            ldm_x4(qh[ks], smb + AT_QHI + sw);
            ldm_x4(ql[ks], smb + AT_QLO + sw);
        }
    }

    float oacc[8][4];
#pragma unroll
    for (int nf = 0; nf < 8; nf++)
#pragma unroll
        for (int r = 0; r < 4; r++) oacc[nf][r] = 0.0f;
    float m0 = -1e30f, m1 = -1e30f, l0 = 0.0f, l1 = 0.0f;

    const int qw = q0 + w * 16;

    for (int ch = 0; ch < ntk; ch++) {
        __syncthreads();
        if (ch + 1 < ntk) load_kv((ch + 1) & 1, ch + 1);
        if (ch + 1 < ntk) { CP_WAIT(1); } else { CP_WAIT(0); }
        __syncthreads();

        const int k0g = ch * 64;
        if (k0g > qw + 15) continue;

        const uint32_t stg = smb + AT_STG + (ch & 1) * 32768;

        float sacc[8][4];
#pragma unroll
        for (int nf = 0; nf < 8; nf++)
#pragma unroll
            for (int r = 0; r < 4; r++) sacc[nf][r] = 0.0f;

        const uint32_t krow = ((lane >> 4) << 3) + (lane & 7);
        const uint32_t kcol = ((lane >> 3) & 1) * 16;
#pragma unroll
        for (int ks = 0; ks < 4; ks++) {
#pragma unroll
            for (int p = 0; p < 4; p++) {
                uint32_t koff = sw128((p * 16 + krow) * 128 + ks * 32 + kcol);
                uint32_t kh[4], kl[4];
                ldm_x4(kh, stg + 0 * 8192 + koff);
                ldm_x4(kl, stg + 1 * 8192 + koff);
                mma16816(sacc[2 * p],     qh[ks], &kh[0]);
                mma16816(sacc[2 * p],     ql[ks], &kh[0]);
                mma16816(sacc[2 * p],     qh[ks], &kl[0]);
                mma16816(sacc[2 * p + 1], qh[ks], &kh[2]);
                mma16816(sacc[2 * p + 1], ql[ks], &kh[2]);
                mma16816(sacc[2 * p + 1], qh[ks], &kl[2]);
            }
        }

        const int r0 = qw + (lane >> 2), r1 = r0 + 8;
        if (k0g + 63 > qw) {
#pragma unroll
            for (int nf = 0; nf < 8; nf++) {
                int key = k0g + nf * 8 + (lane & 3) * 2;
                if (key     > r0) sacc[nf][0] = -1e30f;
                if (key + 1 > r0) sacc[nf][1] = -1e30f;
                if (key     > r1) sacc[nf][2] = -1e30f;
                if (key + 1 > r1) sacc[nf][3] = -1e30f;
            }
        }

        float mx0 = -1e30f, mx1 = -1e30f;
#pragma unroll
        for (int nf = 0; nf < 8; nf++) {
            mx0 = fmaxf(mx0, fmaxf(sacc[nf][0], sacc[nf][1]));
            mx1 = fmaxf(mx1, fmaxf(sacc[nf][2], sacc[nf][3]));
        }
        mx0 = fmaxf(mx0, __shfl_xor_sync(0xffffffffu, mx0, 1));
        mx0 = fmaxf(mx0, __shfl_xor_sync(0xffffffffu, mx0, 2));
        mx1 = fmaxf(mx1, __shfl_xor_sync(0xffffffffu, mx1, 1));
        mx1 = fmaxf(mx1, __shfl_xor_sync(0xffffffffu, mx1, 2));
        float mn0 = fmaxf(m0, mx0), mn1 = fmaxf(m1, mx1);
        // exp(x) = ex2(x*log2e); fold mn*log2e into one FMA per element
        float mnc0 = mn0 * LOG2E, mnc1 = mn1 * LOG2E;
        float al0 = fex2(fmaf(m0, LOG2E, -mnc0));
        float al1 = fex2(fmaf(m1, LOG2E, -mnc1));
        m0 = mn0; m1 = mn1;

        float rs0 = 0.0f, rs1 = 0.0f;
#pragma unroll
        for (int nf = 0; nf < 8; nf++) {
            sacc[nf][0] = fex2(fmaf(sacc[nf][0], LOG2E, -mnc0));
            sacc[nf][1] = fex2(fmaf(sacc[nf][1], LOG2E, -mnc0));
            sacc[nf][2] = fex2(fmaf(sacc[nf][2], LOG2E, -mnc1));
            sacc[nf][3] = fex2(fmaf(sacc[nf][3], LOG2E, -mnc1));
            rs0 += sacc[nf][0] + sacc[nf][1];
            rs1 += sacc[nf][2] + sacc[nf][3];
        }
        rs0 += __shfl_xor_sync(0xffffffffu, rs0, 1);
        rs0 += __shfl_xor_sync(0xffffffffu, rs0, 2);
        rs1 += __shfl_xor_sync(0xffffffffu, rs1, 1);
        rs1 += __shfl_xor_sync(0xffffffffu, rs1, 2);
        l0 = l0 * al0 + rs0;
        l1 = l1 * al1 + rs1;

#pragma unroll
        for (int nf = 0; nf < 8; nf++) {
            oacc[nf][0] *= al0; oacc[nf][1] *= al0;
            oacc[nf][2] *= al1; oacc[nf][3] *= al1;
        }

        uint32_t ph[4][4], pl[4][4];
#pragma unroll
        for (int kf = 0; kf < 4; kf++) {
#pragma unroll
            for (int half = 0; half < 2; half++) {
                const float* c = sacc[2 * kf + half];
                uint32_t hA, lA, hB, lB;
                split2(c[0], c[1], hA, lA);
                split2(c[2], c[3], hB, lB);
                ph[kf][half * 2 + 0] = hA;
                ph[kf][half * 2 + 1] = hB;
                pl[kf][half * 2 + 0] = lA;
                pl[kf][half * 2 + 1] = lB;
            }
        }

        const uint32_t vrow = ((lane >> 3) & 1) * 8 + (lane & 7);
        const uint32_t vcol = (lane >> 4) * 16;
#pragma unroll
        for (int kf = 0; kf < 4; kf++) {
#pragma unroll
            for (int nb = 0; nb < 4; nb++) {
                uint32_t voff = sw128((kf * 16 + vrow) * 128 + nb * 32 + vcol);
                uint32_t vh[4], vl[4];
                ldm_x4t(vh, stg + 2 * 8192 + voff);
                ldm_x4t(vl, stg + 3 * 8192 + voff);
                mma16816(oacc[2 * nb],     ph[kf], &vh[0]);
                mma16816(oacc[2 * nb],     pl[kf], &vh[0]);
                mma16816(oacc[2 * nb],     ph[kf], &vl[0]);
                mma16816(oacc[2 * nb + 1], ph[kf], &vh[2]);
                mma16816(oacc[2 * nb + 1], pl[kf], &vh[2]);
                mma16816(oacc[2 * nb + 1], ph[kf], &vl[2]);
            }
        }
    }

    const int b = bh >> 4, h = bh & 15;
    const float inv0 = 1.0f / l0, inv1 = 1.0f / l1;
    const int row0 = q0 + w * 16 + (lane >> 2);
    const size_t off0 = ((size_t)(b * SS + row0)) * D_MODEL + h * DK + (lane & 3) * 2;
    const size_t off1 = off0 + 8 * D_MODEL;
#pragma unroll
    for (int nf = 0; nf < 8; nf++) {
        uint32_t H, L;
        split2(oacc[nf][0] * inv0, oacc[nf][1] * inv0, H, L);
        *(uint32_t*)(g_cx_hi + off0 + nf * 8) = H;
        *(uint32_t*)(g_cx_lo + off0 + nf * 8) = L;
        split2(oacc[nf][2] * inv1, oacc[nf][3] * inv1, H, L);
        *(uint32_t*)(g_cx_hi + off1 + nf * 8) = H;
        *(uint32_t*)(g_cx_lo + off1 + nf * 8) = L;
    }
}

// ---------------------------------------------------------------------------
// Launch
// ---------------------------------------------------------------------------
extern "C" void kernel_launch(void* const* d_in, const int* in_sizes, int n_in,
                              void* d_out, int out_size) {
    const float* q  = (const float*)d_in[0];
    const float* k  = (const float*)d_in[1];
    const float* v  = (const float*)d_in[2];
    const float* Wq = (const float*)d_in[4];
    const float* Wk = (const float*)d_in[5];
    const float* Wv = (const float*)d_in[6];
    const float* Wo = (const float*)d_in[7];
    float* out = (float*)d_out;

    cudaFuncSetAttribute(gemm_qkv_kernel, cudaFuncAttributeMaxDynamicSharedMemorySize, GEMM_SMEM);
    cudaFuncSetAttribute(gemm_out_kernel, cudaFuncAttributeMaxDynamicSharedMemorySize, GEMM_SMEM);
    cudaFuncSetAttribute(attn_tc_kernel, cudaFuncAttributeMaxDynamicSharedMemorySize, AT_SMEM);

    const int nA4 = MTOT * D_MODEL / 4;
    const int nW4 = D_MODEL * D_MODEL / 4;

    split3_kernel<<<dim3((nA4 + 255) / 256, 3), 256>>>(
        (const float4*)q, (const float4*)k, (const float4*)v, nA4);
    split4_kernel<<<dim3((nW4 + 255) / 256, 4), 256>>>(
        (const float4*)Wq, (const float4*)Wk, (const float4*)Wv, (const float4*)Wo, nW4);

    gemm_qkv_kernel<<<dim3(D_MODEL / 128, MTOT / 128, 3), 256, GEMM_SMEM>>>();

    attn_tc_kernel<<<dim3(SS / 128, BB * NH), 256, AT_SMEM>>>();

    gemm_out_kernel<<<dim3(D_MODEL / 128, MTOT / 128), 256, GEMM_SMEM>>>(out);
}